// round 4
// baseline (speedup 1.0000x reference)
#include <cuda_runtime.h>

#define NN 3072u
#define TOTAL_QUADS (NN * NN * 4u)      // 37,748,736 float4 slots
#define UNROLL 8u
#define TPB 256u
// each thread handles UNROLL quads, one per contiguous 1/UNROLL partition:
// keeps every warp's loads/stores perfectly coalesced in each partition.
#define SPAN (TOTAL_QUADS / UNROLL)     // 4,718,592

__device__ int g_code[NN];

// jax x64 disabled: int64-labeled inputs are actually int32.
__global__ void build_code_kernel(const int* __restrict__ cls,
                                  const int* __restrict__ batch) {
    int i = blockIdx.x * blockDim.x + threadIdx.x;
    if (i < (int)NN) {
        int c = cls[i];
        bool ok = (c != 24) && (c != 25) && (c != 26);
        g_code[i] = ok ? batch[i] : (-1 - i);
    }
}

__global__ void __launch_bounds__(TPB)
pair_write_kernel(const float4* __restrict__ z1,   // [N][4] float4
                  const float4* __restrict__ z2,   // [N][4] float4
                  const float* __restrict__ seg,   // [N*N]
                  float4* __restrict__ out)        // [N*N*4]
{
    unsigned base = blockIdx.x * TPB + threadIdx.x;   // < SPAN

    unsigned gid[UNROLL], pr[UNROLL], qq[UNROLL], ii[UNROLL], jj[UNROLL];
    float s[UNROLL];

    // Front-batched independent seg loads (read-once stream -> .cs), MLP=8.
#pragma unroll
    for (unsigned k = 0; k < UNROLL; k++) {
        gid[k] = base + k * SPAN;
        pr[k]  = gid[k] >> 2;
        qq[k]  = gid[k] & 3u;
        s[k]   = __ldcs(seg + pr[k]);
    }

#pragma unroll
    for (unsigned k = 0; k < UNROLL; k++) {
        ii[k] = pr[k] / NN;
        jj[k] = pr[k] - ii[k] * NN;
    }

#pragma unroll
    for (unsigned k = 0; k < UNROLL; k++) {
        // diagonal excluded (seg + eye); invalid nodes carry unique sentinels
        bool hit = (g_code[ii[k]] == g_code[jj[k]])
                 && (s[k] == 0.0f) && (ii[k] != jj[k]);

        // default row = one_hot(0): 1.0 in float 0 of quad 0, else 0
        float4 v = make_float4(qq[k] == 0u ? 1.0f : 0.0f, 0.0f, 0.0f, 0.0f);

        // Real branch: hits are ~3% and spatially clustered (batch sorted),
        // so most warps uniformly skip both z loads -> big L1 traffic cut.
        if (__any_sync(0xFFFFFFFFu, hit)) {
            if (hit) {
                float4 a = z1[ii[k] * 4u + qq[k]];   // 192KB set: L1/L2 hot
                float4 b = z2[jj[k] * 4u + qq[k]];
                v = make_float4(a.x * b.x, a.y * b.y, a.z * b.z, a.w * b.w);
            }
        }

        __stcs(out + gid[k], v);                 // 604MB write stream
    }
}

extern "C" void kernel_launch(void* const* d_in, const int* in_sizes, int n_in,
                              void* d_out, int out_size) {
    const float4* z1    = (const float4*)d_in[0];
    const float4* z2    = (const float4*)d_in[1];
    const float*  seg   = (const float*)d_in[2];
    const int*    cls   = (const int*)d_in[3];
    const int*    batch = (const int*)d_in[4];
    float4*       out   = (float4*)d_out;

    build_code_kernel<<<((int)NN + (int)TPB - 1) / (int)TPB, TPB>>>(cls, batch);

    pair_write_kernel<<<SPAN / TPB, TPB>>>(z1, z2, seg, out);
}

// round 5
// speedup vs baseline: 1.0603x; 1.0603x over previous
#include <cuda_runtime.h>

#define NN 3072u
#define NPAIRS (NN * NN)                 // 9,437,184
#define TOTAL_QUADS (NPAIRS * 4u)        // 37,748,736 float4 slots
#define UNROLL 4u
#define TPB 256u
#define SPAN (TOTAL_QUADS / UNROLL)      // 9,437,184

// Scratch via __device__ globals (allocation rules).
__device__ int           g_code[NN];
__device__ unsigned char g_mask[NPAIRS]; // 9.4MB: fits in L2, hot for kernel B

// jax x64 disabled: the int64-labeled inputs are actually int32.
__global__ void build_code_kernel(const int* __restrict__ cls,
                                  const int* __restrict__ batch) {
    int i = blockIdx.x * blockDim.x + threadIdx.x;
    if (i < (int)NN) {
        int c = cls[i];
        bool ok = (c != 24) && (c != 25) && (c != 26);
        g_code[i] = ok ? batch[i] : (-1 - i);   // unique sentinel for invalid
    }
}

// Kernel A: read the 38MB seg stream ONCE, write the 9.4MB pair mask.
// Thread t handles 4 consecutive pairs of one row (3072 % 4 == 0):
// one float4 seg load -> one uchar4 mask store. Pure read-mostly phase.
__global__ void __launch_bounds__(TPB)
build_mask_kernel(const float4* __restrict__ seg4) {
    unsigned t  = blockIdx.x * TPB + threadIdx.x;    // < NPAIRS/4
    unsigned i  = t / (NN / 4u);
    unsigned j0 = (t - i * (NN / 4u)) * 4u;

    float4 s = __ldcs(seg4 + t);
    int ci = g_code[i];

    uchar4 m;
    m.x = (ci == g_code[j0 + 0u]) && (s.x == 0.0f) && (i != j0 + 0u);
    m.y = (ci == g_code[j0 + 1u]) && (s.y == 0.0f) && (i != j0 + 1u);
    m.z = (ci == g_code[j0 + 2u]) && (s.z == 0.0f) && (i != j0 + 2u);
    m.w = (ci == g_code[j0 + 3u]) && (s.w == 0.0f) && (i != j0 + 3u);

    *reinterpret_cast<uchar4*>(g_mask + 4u * t) = m;  // stays L2-resident
}

// Kernel B: pure DRAM write stream. Mask + z1/z2 are L2/L1 resident, so the
// DRAM controller sees writes only -> no read/write turnaround loss.
// R3-best shape: UNROLL 4 partitions, thread per float4, fully coalesced.
__global__ void __launch_bounds__(TPB)
pair_write_kernel(const float4* __restrict__ z1,   // [N][4] float4
                  const float4* __restrict__ z2,   // [N][4] float4
                  float4* __restrict__ out)        // [N*N*4]
{
    unsigned base = blockIdx.x * TPB + threadIdx.x;   // < SPAN

    unsigned gid[UNROLL], pr[UNROLL], qq[UNROLL];
    unsigned char m[UNROLL];

#pragma unroll
    for (unsigned k = 0; k < UNROLL; k++) {
        gid[k] = base + k * SPAN;
        pr[k]  = gid[k] >> 2;
        qq[k]  = gid[k] & 3u;
        m[k]   = g_mask[pr[k]];          // L2 hit (written by kernel A)
    }

#pragma unroll
    for (unsigned k = 0; k < UNROLL; k++) {
        float4 v = make_float4(qq[k] == 0u ? 1.0f : 0.0f, 0.0f, 0.0f, 0.0f);
        if (m[k]) {
            unsigned i = pr[k] / NN;
            unsigned j = pr[k] - i * NN;
            float4 a = z1[i * 4u + qq[k]];   // 192KB working set: cache-hot
            float4 b = z2[j * 4u + qq[k]];
            v = make_float4(a.x * b.x, a.y * b.y, a.z * b.z, a.w * b.w);
        }
        __stcs(out + gid[k], v);             // 604MB pure write stream
    }
}

extern "C" void kernel_launch(void* const* d_in, const int* in_sizes, int n_in,
                              void* d_out, int out_size) {
    const float4* z1    = (const float4*)d_in[0];
    const float4* z2    = (const float4*)d_in[1];
    const float4* seg4  = (const float4*)d_in[2];
    const int*    cls   = (const int*)d_in[3];
    const int*    batch = (const int*)d_in[4];
    float4*       out   = (float4*)d_out;

    build_code_kernel<<<((int)NN + (int)TPB - 1) / (int)TPB, TPB>>>(cls, batch);
    build_mask_kernel<<<(NPAIRS / 4u) / TPB, TPB>>>(seg4);
    pair_write_kernel<<<SPAN / TPB, TPB>>>(z1, z2, out);
}

// round 6
// speedup vs baseline: 1.0820x; 1.0205x over previous
#include <cuda_runtime.h>

#define NN 3072u
#define NPAIRS (NN * NN)                 // 9,437,184
#define TOTAL_QUADS (NPAIRS * 4u)        // 37,748,736 float4 slots
#define UNROLL 4u
#define TPB 256u
#define SPAN (TOTAL_QUADS / UNROLL)      // 9,437,184

// Scratch via __device__ global (allocation rules).
__device__ unsigned char g_mask[NPAIRS]; // 9.4MB: L2-resident for kernel B

// node code: batch id if class valid, unique negative sentinel otherwise.
// jax x64 disabled: the "int64" inputs are actually int32.
__device__ __forceinline__ int node_code(int c, int b, unsigned idx) {
    bool ok = (c != 24) && (c != 25) && (c != 26);
    return ok ? b : (int)(-1 - (int)idx);
}

// Kernel A: stream seg once (38MB read), emit pair mask (9.4MB, stays in L2).
// Thread t handles 4 consecutive pairs of one row; node codes are computed
// inline from cls/batch (24KB total -> cache-hot; j-side is one int4 each).
__global__ void __launch_bounds__(TPB)
build_mask_kernel(const float4* __restrict__ seg4,
                  const int* __restrict__ cls,
                  const int* __restrict__ batch) {
    unsigned t  = blockIdx.x * TPB + threadIdx.x;    // < NPAIRS/4
    unsigned i  = t / (NN / 4u);
    unsigned j0 = (t - i * (NN / 4u)) * 4u;

    float4 s = __ldcs(seg4 + t);

    int  ci = node_code(__ldg(cls + i), __ldg(batch + i), i);
    int4 cj = *reinterpret_cast<const int4*>(cls + j0);
    int4 bj = *reinterpret_cast<const int4*>(batch + j0);

    uchar4 m;
    m.x = (ci == node_code(cj.x, bj.x, j0 + 0u)) && (s.x == 0.0f) && (i != j0 + 0u);
    m.y = (ci == node_code(cj.y, bj.y, j0 + 1u)) && (s.y == 0.0f) && (i != j0 + 1u);
    m.z = (ci == node_code(cj.z, bj.z, j0 + 2u)) && (s.z == 0.0f) && (i != j0 + 2u);
    m.w = (ci == node_code(cj.w, bj.w, j0 + 3u)) && (s.w == 0.0f) && (i != j0 + 3u);

    *reinterpret_cast<uchar4*>(g_mask + 4u * t) = m;  // L2-resident hand-off
}

// Kernel B: pure DRAM write stream (mask + z1/z2 are cache-resident).
// R3-best shape: thread per float4, UNROLL 4 contiguous partitions.
__global__ void __launch_bounds__(TPB)
pair_write_kernel(const float4* __restrict__ z1,   // [N][4] float4
                  const float4* __restrict__ z2,   // [N][4] float4
                  float4* __restrict__ out)        // [N*N*4]
{
    unsigned base = blockIdx.x * TPB + threadIdx.x;   // < SPAN

    unsigned gid[UNROLL], pr[UNROLL], qq[UNROLL];
    unsigned char m[UNROLL];

#pragma unroll
    for (unsigned k = 0; k < UNROLL; k++) {
        gid[k] = base + k * SPAN;
        pr[k]  = gid[k] >> 2;
        qq[k]  = gid[k] & 3u;
        m[k]   = g_mask[pr[k]];          // L2 hit (written by kernel A)
    }

#pragma unroll
    for (unsigned k = 0; k < UNROLL; k++) {
        float4 v = make_float4(qq[k] == 0u ? 1.0f : 0.0f, 0.0f, 0.0f, 0.0f);
        if (m[k]) {
            unsigned i = pr[k] / NN;
            unsigned j = pr[k] - i * NN;
            float4 a = z1[i * 4u + qq[k]];   // 192KB working set: cache-hot
            float4 b = z2[j * 4u + qq[k]];
            v = make_float4(a.x * b.x, a.y * b.y, a.z * b.z, a.w * b.w);
        }
        __stcs(out + gid[k], v);             // 604MB pure write stream
    }
}

extern "C" void kernel_launch(void* const* d_in, const int* in_sizes, int n_in,
                              void* d_out, int out_size) {
    const float4* z1    = (const float4*)d_in[0];
    const float4* z2    = (const float4*)d_in[1];
    const float4* seg4  = (const float4*)d_in[2];
    const int*    cls   = (const int*)d_in[3];
    const int*    batch = (const int*)d_in[4];
    float4*       out   = (float4*)d_out;

    build_mask_kernel<<<(NPAIRS / 4u) / TPB, TPB>>>(seg4, cls, batch);
    pair_write_kernel<<<SPAN / TPB, TPB>>>(z1, z2, out);
}

// round 8
// speedup vs baseline: 1.1051x; 1.0213x over previous
#include <cuda_runtime.h>

#define NN 3072u
#define NPAIRS (NN * NN)                 // 9,437,184
#define TOTAL_QUADS (NPAIRS * 4u)        // 37,748,736 float4 slots
#define UNROLL 4u
#define TPB 256u
#define SPAN (TOTAL_QUADS / UNROLL)      // 9,437,184

// Bit-packed pair mask: 1 bit per pair, 1.2MB -> L2-resident for kernel B.
__device__ unsigned char g_bits[NPAIRS / 8u];

// node code: batch id if class valid, unique negative sentinel otherwise.
// jax x64 disabled: the "int64" inputs are actually int32.
__device__ __forceinline__ int node_code(int c, int b, unsigned idx) {
    bool ok = (c != 24) && (c != 25) && (c != 26);
    return ok ? b : (int)(-1 - (int)idx);
}

// Kernel A: stream seg once (38MB read), emit bit-packed mask (1.2MB).
// Thread t handles 8 consecutive pairs of one row (NN % 8 == 0):
// two float4 seg loads (MLP=2) -> one byte store.
__global__ void __launch_bounds__(TPB)
build_mask_kernel(const float4* __restrict__ seg4,
                  const int* __restrict__ cls,
                  const int* __restrict__ batch) {
    unsigned t  = blockIdx.x * TPB + threadIdx.x;    // < NPAIRS/8
    unsigned i  = t / (NN / 8u);
    unsigned j0 = (t - i * (NN / 8u)) * 8u;

    float4 s0 = __ldcs(seg4 + 2u * t);
    float4 s1 = __ldcs(seg4 + 2u * t + 1u);

    int ci = node_code(__ldg(cls + i), __ldg(batch + i), i);

    int4 cj0 = *reinterpret_cast<const int4*>(cls + j0);
    int4 cj1 = *reinterpret_cast<const int4*>(cls + j0 + 4u);
    int4 bj0 = *reinterpret_cast<const int4*>(batch + j0);
    int4 bj1 = *reinterpret_cast<const int4*>(batch + j0 + 4u);

    unsigned byte = 0u;
    byte |= (unsigned)((ci == node_code(cj0.x, bj0.x, j0 + 0u)) && (s0.x == 0.0f) && (i != j0 + 0u)) << 0;
    byte |= (unsigned)((ci == node_code(cj0.y, bj0.y, j0 + 1u)) && (s0.y == 0.0f) && (i != j0 + 1u)) << 1;
    byte |= (unsigned)((ci == node_code(cj0.z, bj0.z, j0 + 2u)) && (s0.z == 0.0f) && (i != j0 + 2u)) << 2;
    byte |= (unsigned)((ci == node_code(cj0.w, bj0.w, j0 + 3u)) && (s0.w == 0.0f) && (i != j0 + 3u)) << 3;
    byte |= (unsigned)((ci == node_code(cj1.x, bj1.x, j0 + 4u)) && (s1.x == 0.0f) && (i != j0 + 4u)) << 4;
    byte |= (unsigned)((ci == node_code(cj1.y, bj1.y, j0 + 5u)) && (s1.y == 0.0f) && (i != j0 + 5u)) << 5;
    byte |= (unsigned)((ci == node_code(cj1.z, bj1.z, j0 + 6u)) && (s1.z == 0.0f) && (i != j0 + 6u)) << 6;
    byte |= (unsigned)((ci == node_code(cj1.w, bj1.w, j0 + 7u)) && (s1.w == 0.0f) && (i != j0 + 7u)) << 7;

    g_bits[t] = (unsigned char)byte;     // L2-resident hand-off
}

// Kernel B: pure DRAM write stream (mask bits + z1/z2 cache-resident).
// Thread per float4, UNROLL 4 contiguous partitions (R3-proven shape).
// A warp's 8 pairs map to a single mask byte -> uniform broadcast load.
__global__ void __launch_bounds__(TPB)
pair_write_kernel(const float4* __restrict__ z1,   // [N][4] float4
                  const float4* __restrict__ z2,   // [N][4] float4
                  float4* __restrict__ out)        // [N*N*4]
{
    unsigned base = blockIdx.x * TPB + threadIdx.x;   // < SPAN

    unsigned gid[UNROLL], pr[UNROLL], qq[UNROLL];
    unsigned mb[UNROLL];

#pragma unroll
    for (unsigned k = 0; k < UNROLL; k++) {
        gid[k] = base + k * SPAN;
        pr[k]  = gid[k] >> 2;
        qq[k]  = gid[k] & 3u;
        mb[k]  = (unsigned)g_bits[pr[k] >> 3];   // L2 hit, warp-uniform
    }

#pragma unroll
    for (unsigned k = 0; k < UNROLL; k++) {
        float4 v = make_float4(qq[k] == 0u ? 1.0f : 0.0f, 0.0f, 0.0f, 0.0f);
        if ((mb[k] >> (pr[k] & 7u)) & 1u) {
            unsigned i = pr[k] / NN;
            unsigned j = pr[k] - i * NN;
            float4 a = z1[i * 4u + qq[k]];   // 192KB working set: cache-hot
            float4 b = z2[j * 4u + qq[k]];
            v = make_float4(a.x * b.x, a.y * b.y, a.z * b.z, a.w * b.w);
        }
        __stcs(out + gid[k], v);             // 604MB pure write stream
    }
}

extern "C" void kernel_launch(void* const* d_in, const int* in_sizes, int n_in,
                              void* d_out, int out_size) {
    const float4* z1    = (const float4*)d_in[0];
    const float4* z2    = (const float4*)d_in[1];
    const float4* seg4  = (const float4*)d_in[2];
    const int*    cls   = (const int*)d_in[3];
    const int*    batch = (const int*)d_in[4];
    float4*       out   = (float4*)d_out;

    build_mask_kernel<<<(NPAIRS / 8u) / TPB, TPB>>>(seg4, cls, batch);
    pair_write_kernel<<<SPAN / TPB, TPB>>>(z1, z2, out);
}